// round 10
// baseline (speedup 1.0000x reference)
#include <cuda_runtime.h>
#include <cub/cub.cuh>

#define NPOS    16384
#define NANCH   147456
#define NOUTC   54
#define MAXOUT  2000

// ---------------- scratch (static device globals; no allocation) ----------------
__device__ float g_logits[NPOS * NOUTC];   // GEMM output (16384 x 54)
__device__ float g_sc[NANCH];              // scores
__device__ float g_x0[NANCH];
__device__ float g_y0[NANCH];
__device__ float g_x1[NANCH];
__device__ float g_y1[NANCH];
__device__ float g_ar[NANCH];
__device__ int   g_idx[NANCH];
__device__ float g_scs[NANCH];             // sorted scores
__device__ int   g_idxs[NANCH];            // sorted indices
__device__ unsigned char g_tmp[8 << 20];   // cub temp storage

// Unfused Cephes exp (exp variants proven output-invariant in rounds 4-7).
__device__ __forceinline__ float cephes_expf(float xin) {
  float x = fminf(xin, 88.3762626647950f);
  x = fmaxf(x, -88.3762626647949f);
  float fx = floorf(__fadd_rn(__fmul_rn(x, 1.44269504088896341f), 0.5f));
  float tmp = __fmul_rn(fx, 0.693359375f);
  float z   = __fmul_rn(fx, -2.12194440e-4f);
  x = __fsub_rn(x, tmp);
  x = __fsub_rn(x, z);
  z = __fmul_rn(x, x);
  float y = 1.9875691500E-4f;
  y = __fadd_rn(__fmul_rn(y, x), 1.3981999507E-3f);
  y = __fadd_rn(__fmul_rn(y, x), 8.3334519073E-3f);
  y = __fadd_rn(__fmul_rn(y, x), 4.1665795894E-2f);
  y = __fadd_rn(__fmul_rn(y, x), 1.6666665459E-1f);
  y = __fadd_rn(__fmul_rn(y, x), 5.0000001201E-1f);
  y = __fadd_rn(__fmul_rn(y, z), x);
  y = __fadd_rn(y, 1.0f);
  int n = (int)fx;
  float two_n = __int_as_float((n + 127) << 23);
  return __fmul_rn(y, two_n);
}

// ---------------- GEMM: (16384 x 1024) * (1024 x 54) ----------------
// cublas sliced1x4 accumulation replica: 4 k-slices, slice s owns the
// INTERLEAVED sub-tiles k in [32t+8s, 32t+8s+8) for all t (strided at
// granularity 8). Each slice is a private sequential FMA chain; slices are
// combined at the end with sequential rounded adds ((p0+p1)+p2)+p3.
__global__ void __launch_bounds__(256) gemm_kernel(
    const float* __restrict__ A,
    const float* __restrict__ Wc, const float* __restrict__ Bc,
    const float* __restrict__ Wb, const float* __restrict__ Bb) {
  __shared__ float As[64][33];   // [m][k], padded
  __shared__ float Bs[32][64];   // [k][n]
  const int tid = threadIdx.x;
  const int m0  = blockIdx.x * 64;
  const int tm  = tid & 15;      // m-group: rows tm*4 .. tm*4+3
  const int tn  = tid >> 4;      // n-group: cols tn*4 .. tn*4+3
  const int kq  = tid & 7;       // A-load: k-quad
  const int mr  = tid >> 3;      // A-load: row (0..31, +32)

  float cur[4][4][4];   // [slice][mi][nj] — 4 independent k-slice partials
#pragma unroll
  for (int s = 0; s < 4; ++s)
#pragma unroll
    for (int i = 0; i < 4; ++i)
#pragma unroll
      for (int j = 0; j < 4; ++j) cur[s][i][j] = 0.f;

  for (int k0 = 0; k0 < 1024; k0 += 32) {
    float4 va = *(const float4*)(A + (size_t)(m0 + mr) * 1024 + k0 + kq * 4);
    float4 vb = *(const float4*)(A + (size_t)(m0 + mr + 32) * 1024 + k0 + kq * 4);
    As[mr][kq * 4 + 0] = va.x; As[mr][kq * 4 + 1] = va.y;
    As[mr][kq * 4 + 2] = va.z; As[mr][kq * 4 + 3] = va.w;
    As[mr + 32][kq * 4 + 0] = vb.x; As[mr + 32][kq * 4 + 1] = vb.y;
    As[mr + 32][kq * 4 + 2] = vb.z; As[mr + 32][kq * 4 + 3] = vb.w;
#pragma unroll
    for (int i = 0; i < 8; ++i) {
      int e = i * 256 + tid;
      int k = e >> 6, n = e & 63;
      float w = 0.f;
      if (n < 18)      w = Wc[(size_t)(k0 + k) * 18 + n];
      else if (n < 54) w = Wb[(size_t)(k0 + k) * 36 + (n - 18)];
      Bs[k][n] = w;
    }
    __syncthreads();
#pragma unroll
    for (int g = 0; g < 4; ++g) {   // slice g handles k-subtile [8g, 8g+8)
#pragma unroll
      for (int kk = 0; kk < 8; ++kk) {
        int k = g * 8 + kk;
        float4 b4 = *(const float4*)&Bs[k][tn * 4];
        float a0 = As[tm * 4 + 0][k];
        float a1 = As[tm * 4 + 1][k];
        float a2 = As[tm * 4 + 2][k];
        float a3 = As[tm * 4 + 3][k];
        cur[g][0][0] = fmaf(a0, b4.x, cur[g][0][0]); cur[g][0][1] = fmaf(a0, b4.y, cur[g][0][1]);
        cur[g][0][2] = fmaf(a0, b4.z, cur[g][0][2]); cur[g][0][3] = fmaf(a0, b4.w, cur[g][0][3]);
        cur[g][1][0] = fmaf(a1, b4.x, cur[g][1][0]); cur[g][1][1] = fmaf(a1, b4.y, cur[g][1][1]);
        cur[g][1][2] = fmaf(a1, b4.z, cur[g][1][2]); cur[g][1][3] = fmaf(a1, b4.w, cur[g][1][3]);
        cur[g][2][0] = fmaf(a2, b4.x, cur[g][2][0]); cur[g][2][1] = fmaf(a2, b4.y, cur[g][2][1]);
        cur[g][2][2] = fmaf(a2, b4.z, cur[g][2][2]); cur[g][2][3] = fmaf(a2, b4.w, cur[g][2][3]);
        cur[g][3][0] = fmaf(a3, b4.x, cur[g][3][0]); cur[g][3][1] = fmaf(a3, b4.y, cur[g][3][1]);
        cur[g][3][2] = fmaf(a3, b4.z, cur[g][3][2]); cur[g][3][3] = fmaf(a3, b4.w, cur[g][3][3]);
      }
    }
    __syncthreads();
  }
#pragma unroll
  for (int i = 0; i < 4; ++i)
#pragma unroll
    for (int j = 0; j < 4; ++j) {
      int n = tn * 4 + j;
      if (n < 54) {
        // Cross-slice reduction: sequential ascending, then bias.
        float logit = __fadd_rn(cur[0][i][j], cur[1][i][j]);
        logit = __fadd_rn(logit, cur[2][i][j]);
        logit = __fadd_rn(logit, cur[3][i][j]);
        float bias = (n < 18) ? Bc[n] : Bb[n - 18];
        g_logits[(size_t)(m0 + tm * 4 + i) * NOUTC + n] = __fadd_rn(logit, bias);
      }
    }
}

// ---------------- decode: softmax-pair score + box decode/clip ----------------
__global__ void __launch_bounds__(256) decode_kernel(
    const float* __restrict__ anchors, const float* __restrict__ img) {
  int g = blockIdx.x * 256 + threadIdx.x;
  if (g >= NANCH) return;
  int p = g / 9, a = g - p * 9;
  const float* L = g_logits + (size_t)p * NOUTC;
  int c = 9 + a;                  // fg channel; softmax pair partner is c^1
  float la = L[c], lb = L[c ^ 1];
  float m  = fmaxf(la, lb);
  float ea = cephes_expf(__fsub_rn(la, m));
  float eb = cephes_expf(__fsub_rn(lb, m));
  float score = __fdiv_rn(ea, __fadd_rn(ea, eb));

  float tx = L[18 + 4 * a + 0];
  float ty = L[18 + 4 * a + 1];
  float tw = L[18 + 4 * a + 2];
  float th = L[18 + 4 * a + 3];
  float a0 = anchors[4 * g + 0];
  float a1 = anchors[4 * g + 1];
  float a2 = anchors[4 * g + 2];
  float a3 = anchors[4 * g + 3];
  float w  = __fadd_rn(__fsub_rn(a3, a1), 1.0f);
  float h  = __fadd_rn(__fsub_rn(a2, a0), 1.0f);
  float xc = __fadd_rn(a0, __fmul_rn(0.5f, h));
  float yc = __fadd_rn(a1, __fmul_rn(0.5f, w));
  float xp = __fadd_rn(__fmul_rn(tx, h), xc);
  float yp = __fadd_rn(__fmul_rn(ty, w), yc);
  float wp = __fmul_rn(cephes_expf(tw), w);
  float hp = __fmul_rn(cephes_expf(th), h);
  float hh = __fmul_rn(0.5f, hp);
  float hw = __fmul_rn(0.5f, wp);
  float X0 = fmaxf(__fsub_rn(xp, hh), 0.f);
  float X1 = fminf(__fadd_rn(xp, hh), img[0]);
  float Y0 = fmaxf(__fsub_rn(yp, hw), 0.f);
  float Y1 = fminf(__fadd_rn(yp, hw), img[1]);

  g_sc[g] = score;
  g_x0[g] = X0; g_y0[g] = Y0; g_x1[g] = X1; g_y1[g] = Y1;
  g_ar[g] = __fmul_rn(fmaxf(__fsub_rn(X1, X0), 0.f), fmaxf(__fsub_rn(Y1, Y0), 0.f));
  g_idx[g] = g;
}

// IoU test in the reference's exact form and op order.
__device__ __forceinline__ bool iou_gt(float sX0, float sY0, float sX1, float sY1,
                                       float sA, float X0, float Y0, float X1,
                                       float Y1, float Ac) {
  float iw = __fsub_rn(fminf(sX1, X1), fmaxf(sX0, X0));
  float ih = __fsub_rn(fminf(sY1, Y1), fmaxf(sY0, Y0));
  float inter = __fmul_rn(fmaxf(iw, 0.f), fmaxf(ih, 0.f));
  float denom = __fadd_rn(__fsub_rn(__fadd_rn(sA, Ac), inter), 1e-9f);
  return __fdiv_rn(inter, denom) > 0.7f;
}

// ---------------- greedy NMS (single block, serial over sorted candidates) ----------------
__global__ void __launch_bounds__(1024) nms_kernel(float* __restrict__ out, int out_size) {
  extern __shared__ float sm[];
  float* sx0 = sm;                 // selected set (<= 2000)
  float* sy0 = sm + MAXOUT;
  float* sx1 = sm + 2 * MAXOUT;
  float* sy1 = sm + 3 * MAXOUT;
  float* sar = sm + 4 * MAXOUT;
  float* cx0 = sm + 5 * MAXOUT;    // candidate batch cache (1024)
  float* cy0 = cx0 + 1024;
  float* cx1 = cy0 + 1024;
  float* cy1 = cx1 + 1024;
  float* car = cy1 + 1024;
  float* cke = car + 1024;
  const int tid = threadIdx.x;

  for (int i = tid; i < out_size; i += 1024) out[i] = 0.f;

  int ns = 0;
  bool havePrev = false;   // last selection not yet barrier-published to smem readers
  float pX0 = 0.f, pY0 = 0.f, pX1 = 0.f, pY1 = 0.f, pAr = 0.f;

  for (int j = 0; j < NANCH; ++j) {
    if ((j & 1023) == 0) {
      __syncthreads();
      int jj = j + tid;                 // NANCH is a multiple of 1024
      int v  = g_idxs[jj];
      cx0[tid] = g_x0[v];
      cy0[tid] = g_y0[v];
      cx1[tid] = g_x1[v];
      cy1[tid] = g_y1[v];
      car[tid] = g_ar[v];
      cke[tid] = g_scs[jj];
      __syncthreads();
    }
    const int cc = j & 1023;
    const float X0 = cx0[cc], Y0 = cy0[cc], X1 = cx1[cc], Y1 = cy1[cc], Ac = car[cc];
    bool sup = false;
    const int nsafe = ns - (havePrev ? 1 : 0);
    for (int s = tid; s < nsafe; s += 1024) {
      if (iou_gt(sx0[s], sy0[s], sx1[s], sy1[s], sar[s], X0, Y0, X1, Y1, Ac))
        sup = true;
    }
    if (havePrev) {
      if (iou_gt(pX0, pY0, pX1, pY1, pAr, X0, Y0, X1, Y1, Ac)) sup = true;
    }
    int any = __syncthreads_or(sup ? 1 : 0);
    if (!any) {
      if (tid == 0) {
        sx0[ns] = X0; sy0[ns] = Y0; sx1[ns] = X1; sy1[ns] = Y1; sar[ns] = Ac;
        if (ns * 4 + 3 < out_size) {
          out[ns * 4 + 0] = X0; out[ns * 4 + 1] = Y0;
          out[ns * 4 + 2] = X1; out[ns * 4 + 3] = Y1;
        }
        int so = MAXOUT * 4 + ns;
        if (so < out_size) out[so] = cke[cc];
      }
      pX0 = X0; pY0 = Y0; pX1 = X1; pY1 = Y1; pAr = Ac;
      havePrev = true;
      ++ns;
      if (ns >= MAXOUT) break;
    } else {
      havePrev = false;
    }
  }
}

// ---------------- launch ----------------
extern "C" void kernel_launch(void* const* d_in, const int* in_sizes, int n_in,
                              void* d_out, int out_size) {
  const float* feat    = (const float*)d_in[0];
  const float* anchors = (const float*)d_in[1];
  const float* img     = (const float*)d_in[2];
  const float* wcls    = (const float*)d_in[3];
  const float* bcls    = (const float*)d_in[4];
  const float* wbbox   = (const float*)d_in[5];
  const float* bbbox   = (const float*)d_in[6];
  float* out = (float*)d_out;

  float *p_sc, *p_scs;
  int   *p_idx, *p_idxs;
  void  *p_tmp;
  cudaGetSymbolAddress((void**)&p_sc,   g_sc);
  cudaGetSymbolAddress((void**)&p_scs,  g_scs);
  cudaGetSymbolAddress((void**)&p_idx,  g_idx);
  cudaGetSymbolAddress((void**)&p_idxs, g_idxs);
  cudaGetSymbolAddress(&p_tmp,          g_tmp);

  gemm_kernel<<<NPOS / 64, 256>>>(feat, wcls, bcls, wbbox, bbbox);
  decode_kernel<<<(NANCH + 255) / 256, 256>>>(anchors, img);

  // Scores are softmax outputs in (0,1): IEEE bits are positive with bits 30-31
  // identically zero across all keys, so a 30-bit descending radix sort is exact.
  size_t tmp_bytes = sizeof(g_tmp);
  cub::DeviceRadixSort::SortPairsDescending(p_tmp, tmp_bytes, p_sc, p_scs,
                                            p_idx, p_idxs, NANCH, 0, 30);

  const int nms_smem = (5 * MAXOUT + 6 * 1024) * (int)sizeof(float);
  cudaFuncSetAttribute(nms_kernel, cudaFuncAttributeMaxDynamicSharedMemorySize, nms_smem);
  nms_kernel<<<1, 1024, nms_smem>>>(out, out_size);
}

// round 11
// speedup vs baseline: 2.5104x; 2.5104x over previous
#include <cuda_runtime.h>
#include <cub/cub.cuh>

#define NPOS    16384
#define NANCH   147456
#define NOUTC   54
#define MAXOUT  2000

// ---------------- scratch (static device globals; no allocation) ----------------
__device__ float g_logits[NPOS * NOUTC];   // GEMM output (16384 x 54)
__device__ float g_sc[NANCH];              // scores
__device__ float g_x0[NANCH];
__device__ float g_y0[NANCH];
__device__ float g_x1[NANCH];
__device__ float g_y1[NANCH];
__device__ float g_ar[NANCH];
__device__ int   g_idx[NANCH];
__device__ float g_scs[NANCH];             // sorted scores
__device__ int   g_idxs[NANCH];            // sorted indices
__device__ unsigned char g_tmp[8 << 20];   // cub temp storage

// Unfused Cephes exp (exp variants proven output-invariant in rounds 4-7).
__device__ __forceinline__ float cephes_expf(float xin) {
  float x = fminf(xin, 88.3762626647950f);
  x = fmaxf(x, -88.3762626647949f);
  float fx = floorf(__fadd_rn(__fmul_rn(x, 1.44269504088896341f), 0.5f));
  float tmp = __fmul_rn(fx, 0.693359375f);
  float z   = __fmul_rn(fx, -2.12194440e-4f);
  x = __fsub_rn(x, tmp);
  x = __fsub_rn(x, z);
  z = __fmul_rn(x, x);
  float y = 1.9875691500E-4f;
  y = __fadd_rn(__fmul_rn(y, x), 1.3981999507E-3f);
  y = __fadd_rn(__fmul_rn(y, x), 8.3334519073E-3f);
  y = __fadd_rn(__fmul_rn(y, x), 4.1665795894E-2f);
  y = __fadd_rn(__fmul_rn(y, x), 1.6666665459E-1f);
  y = __fadd_rn(__fmul_rn(y, x), 5.0000001201E-1f);
  y = __fadd_rn(__fmul_rn(y, z), x);
  y = __fadd_rn(y, 1.0f);
  int n = (int)fx;
  float two_n = __int_as_float((n + 127) << 23);
  return __fmul_rn(y, two_n);
}

// ---------------- GEMM: (16384 x 1024) * (1024 x 54) ----------------
// PROVEN BIT-EXACT vs reference (round 10): cublas sliced1x4 replica —
// 4 k-slices, slice g owns interleaved sub-tiles k in [32t+8g, 32t+8g+8);
// private FMA chains, combined ((p0+p1)+p2)+p3. DO NOT change FMA order.
__global__ void __launch_bounds__(256) gemm_kernel(
    const float* __restrict__ A,
    const float* __restrict__ Wc, const float* __restrict__ Bc,
    const float* __restrict__ Wb, const float* __restrict__ Bb) {
  __shared__ float As[64][33];   // [m][k], padded
  __shared__ float Bs[32][64];   // [k][n]
  const int tid = threadIdx.x;
  const int m0  = blockIdx.x * 64;
  const int tm  = tid & 15;      // m-group: rows tm*4 .. tm*4+3
  const int tn  = tid >> 4;      // n-group: cols tn*4 .. tn*4+3
  const int kq  = tid & 7;       // A-load: k-quad
  const int mr  = tid >> 3;      // A-load: row (0..31, +32)

  float cur[4][4][4];   // [slice][mi][nj]
#pragma unroll
  for (int s = 0; s < 4; ++s)
#pragma unroll
    for (int i = 0; i < 4; ++i)
#pragma unroll
      for (int j = 0; j < 4; ++j) cur[s][i][j] = 0.f;

  for (int k0 = 0; k0 < 1024; k0 += 32) {
    float4 va = *(const float4*)(A + (size_t)(m0 + mr) * 1024 + k0 + kq * 4);
    float4 vb = *(const float4*)(A + (size_t)(m0 + mr + 32) * 1024 + k0 + kq * 4);
    As[mr][kq * 4 + 0] = va.x; As[mr][kq * 4 + 1] = va.y;
    As[mr][kq * 4 + 2] = va.z; As[mr][kq * 4 + 3] = va.w;
    As[mr + 32][kq * 4 + 0] = vb.x; As[mr + 32][kq * 4 + 1] = vb.y;
    As[mr + 32][kq * 4 + 2] = vb.z; As[mr + 32][kq * 4 + 3] = vb.w;
#pragma unroll
    for (int i = 0; i < 8; ++i) {
      int e = i * 256 + tid;
      int k = e >> 6, n = e & 63;
      float w = 0.f;
      if (n < 18)      w = Wc[(size_t)(k0 + k) * 18 + n];
      else if (n < 54) w = Wb[(size_t)(k0 + k) * 36 + (n - 18)];
      Bs[k][n] = w;
    }
    __syncthreads();
#pragma unroll
    for (int g = 0; g < 4; ++g) {   // slice g: k-subtile [8g, 8g+8)
#pragma unroll
      for (int kk = 0; kk < 8; ++kk) {
        int k = g * 8 + kk;
        float4 b4 = *(const float4*)&Bs[k][tn * 4];
        float a0 = As[tm * 4 + 0][k];
        float a1 = As[tm * 4 + 1][k];
        float a2 = As[tm * 4 + 2][k];
        float a3 = As[tm * 4 + 3][k];
        cur[g][0][0] = fmaf(a0, b4.x, cur[g][0][0]); cur[g][0][1] = fmaf(a0, b4.y, cur[g][0][1]);
        cur[g][0][2] = fmaf(a0, b4.z, cur[g][0][2]); cur[g][0][3] = fmaf(a0, b4.w, cur[g][0][3]);
        cur[g][1][0] = fmaf(a1, b4.x, cur[g][1][0]); cur[g][1][1] = fmaf(a1, b4.y, cur[g][1][1]);
        cur[g][1][2] = fmaf(a1, b4.z, cur[g][1][2]); cur[g][1][3] = fmaf(a1, b4.w, cur[g][1][3]);
        cur[g][2][0] = fmaf(a2, b4.x, cur[g][2][0]); cur[g][2][1] = fmaf(a2, b4.y, cur[g][2][1]);
        cur[g][2][2] = fmaf(a2, b4.z, cur[g][2][2]); cur[g][2][3] = fmaf(a2, b4.w, cur[g][2][3]);
        cur[g][3][0] = fmaf(a3, b4.x, cur[g][3][0]); cur[g][3][1] = fmaf(a3, b4.y, cur[g][3][1]);
        cur[g][3][2] = fmaf(a3, b4.z, cur[g][3][2]); cur[g][3][3] = fmaf(a3, b4.w, cur[g][3][3]);
      }
    }
    __syncthreads();
  }
#pragma unroll
  for (int i = 0; i < 4; ++i)
#pragma unroll
    for (int j = 0; j < 4; ++j) {
      int n = tn * 4 + j;
      if (n < 54) {
        float logit = __fadd_rn(cur[0][i][j], cur[1][i][j]);
        logit = __fadd_rn(logit, cur[2][i][j]);
        logit = __fadd_rn(logit, cur[3][i][j]);
        float bias = (n < 18) ? Bc[n] : Bb[n - 18];
        g_logits[(size_t)(m0 + tm * 4 + i) * NOUTC + n] = __fadd_rn(logit, bias);
      }
    }
}

// ---------------- decode: softmax-pair score + box decode/clip ----------------
__global__ void __launch_bounds__(256) decode_kernel(
    const float* __restrict__ anchors, const float* __restrict__ img) {
  int g = blockIdx.x * 256 + threadIdx.x;
  if (g >= NANCH) return;
  int p = g / 9, a = g - p * 9;
  const float* L = g_logits + (size_t)p * NOUTC;
  int c = 9 + a;
  float la = L[c], lb = L[c ^ 1];
  float m  = fmaxf(la, lb);
  float ea = cephes_expf(__fsub_rn(la, m));
  float eb = cephes_expf(__fsub_rn(lb, m));
  float score = __fdiv_rn(ea, __fadd_rn(ea, eb));

  float tx = L[18 + 4 * a + 0];
  float ty = L[18 + 4 * a + 1];
  float tw = L[18 + 4 * a + 2];
  float th = L[18 + 4 * a + 3];
  float a0 = anchors[4 * g + 0];
  float a1 = anchors[4 * g + 1];
  float a2 = anchors[4 * g + 2];
  float a3 = anchors[4 * g + 3];
  float w  = __fadd_rn(__fsub_rn(a3, a1), 1.0f);
  float h  = __fadd_rn(__fsub_rn(a2, a0), 1.0f);
  float xc = __fadd_rn(a0, __fmul_rn(0.5f, h));
  float yc = __fadd_rn(a1, __fmul_rn(0.5f, w));
  float xp = __fadd_rn(__fmul_rn(tx, h), xc);
  float yp = __fadd_rn(__fmul_rn(ty, w), yc);
  float wp = __fmul_rn(cephes_expf(tw), w);
  float hp = __fmul_rn(cephes_expf(th), h);
  float hh = __fmul_rn(0.5f, hp);
  float hw = __fmul_rn(0.5f, wp);
  float X0 = fmaxf(__fsub_rn(xp, hh), 0.f);
  float X1 = fminf(__fadd_rn(xp, hh), img[0]);
  float Y0 = fmaxf(__fsub_rn(yp, hw), 0.f);
  float Y1 = fminf(__fadd_rn(yp, hw), img[1]);

  g_sc[g] = score;
  g_x0[g] = X0; g_y0[g] = Y0; g_x1[g] = X1; g_y1[g] = Y1;
  g_ar[g] = __fmul_rn(fmaxf(__fsub_rn(X1, X0), 0.f), fmaxf(__fsub_rn(Y1, Y0), 0.f));
  g_idx[g] = g;
}

// IoU test in the reference's exact form and op order (fully symmetric in
// the two boxes, so suppressor/candidate roles are interchangeable).
__device__ __forceinline__ bool iou_gt(float sX0, float sY0, float sX1, float sY1,
                                       float sA, float X0, float Y0, float X1,
                                       float Y1, float Ac) {
  float iw = __fsub_rn(fminf(sX1, X1), fmaxf(sX0, X0));
  float ih = __fsub_rn(fminf(sY1, Y1), fmaxf(sY0, Y0));
  float inter = __fmul_rn(fmaxf(iw, 0.f), fmaxf(ih, 0.f));
  float denom = __fadd_rn(__fsub_rn(__fadd_rn(sA, Ac), inter), 1e-9f);
  return __fdiv_rn(inter, denom) > 0.7f;
}

// ---------------- greedy NMS: warp-per-candidate batched (decision-sequence
// identical to the proven serial loop) ----------------
// Batch of 32 candidates; warp w tests candidate w against the selected set
// (lanes stride S); lane l computes the intra-batch suppression bit
// IoU(cand_l, cand_w) for l<w. Warp 0 resolves the greedy recurrence over the
// 32-bit alive mask (alive iff not suppressed by S nor by an earlier ALIVE
// batchmate), then appends alive candidates in order via prefix popcount.
__global__ void __launch_bounds__(1024) nms_kernel(float* __restrict__ out, int out_size) {
  __shared__ float sx0[MAXOUT], sy0[MAXOUT], sx1[MAXOUT], sy1[MAXOUT], sar[MAXOUT];
  __shared__ float bx0[32], by0[32], bx1[32], by1[32], bar_[32], bsc[32];
  __shared__ int   supS[32];
  __shared__ unsigned rowS[32];
  __shared__ int   ns_sh;
  const int tid  = threadIdx.x;
  const int wid  = tid >> 5;
  const int lane = tid & 31;

  for (int i = tid; i < out_size; i += 1024) out[i] = 0.f;
  if (tid == 0) ns_sh = 0;
  __syncthreads();

  int ns = 0;
  for (int jb = 0; jb < NANCH && ns < MAXOUT; jb += 32) {
    if (tid < 32) {
      int v = g_idxs[jb + tid];
      bx0[tid] = g_x0[v]; by0[tid] = g_y0[v];
      bx1[tid] = g_x1[v]; by1[tid] = g_y1[v];
      bar_[tid] = g_ar[v]; bsc[tid] = g_scs[jb + tid];
    }
    __syncthreads();

    // Warp w: candidate w vs selected set S (lanes stride).
    const float cX0 = bx0[wid], cY0 = by0[wid], cX1 = bx1[wid], cY1 = by1[wid], cA = bar_[wid];
    bool sup = false;
    for (int s = lane; s < ns; s += 32)
      if (iou_gt(sx0[s], sy0[s], sx1[s], sy1[s], sar[s], cX0, cY0, cX1, cY1, cA))
        sup = true;
    unsigned anysup = __any_sync(0xffffffffu, sup);

    // Intra-batch: lane l -> does earlier candidate l suppress candidate w?
    bool ps = false;
    if (lane < wid)
      ps = iou_gt(bx0[lane], by0[lane], bx1[lane], by1[lane], bar_[lane],
                  cX0, cY0, cX1, cY1, cA);
    unsigned prow = __ballot_sync(0xffffffffu, ps);
    if (lane == 0) { supS[wid] = anysup ? 1 : 0; rowS[wid] = prow; }
    __syncthreads();

    // Warp 0: resolve greedy recurrence + append in order.
    if (wid == 0) {
      unsigned alive = 0;
      for (int l = 0; l < 32; ++l)
        if (!supS[l] && ((rowS[l] & alive) == 0u)) alive |= (1u << l);
      int base = ns_sh;
      if ((alive >> lane) & 1u) {
        int pos = base + __popc(alive & ((1u << lane) - 1u));
        if (pos < MAXOUT) {
          sx0[pos] = bx0[lane]; sy0[pos] = by0[lane];
          sx1[pos] = bx1[lane]; sy1[pos] = by1[lane]; sar[pos] = bar_[lane];
          if (pos * 4 + 3 < out_size) {
            out[pos * 4 + 0] = bx0[lane]; out[pos * 4 + 1] = by0[lane];
            out[pos * 4 + 2] = bx1[lane]; out[pos * 4 + 3] = by1[lane];
          }
          int so = 4 * MAXOUT + pos;
          if (so < out_size) out[so] = bsc[lane];
        }
      }
      __syncwarp();
      if (lane == 0) {
        int nn = base + __popc(alive);
        ns_sh = (nn > MAXOUT) ? MAXOUT : nn;
      }
    }
    __syncthreads();
    ns = ns_sh;
  }
}

// ---------------- launch ----------------
extern "C" void kernel_launch(void* const* d_in, const int* in_sizes, int n_in,
                              void* d_out, int out_size) {
  const float* feat    = (const float*)d_in[0];
  const float* anchors = (const float*)d_in[1];
  const float* img     = (const float*)d_in[2];
  const float* wcls    = (const float*)d_in[3];
  const float* bcls    = (const float*)d_in[4];
  const float* wbbox   = (const float*)d_in[5];
  const float* bbbox   = (const float*)d_in[6];
  float* out = (float*)d_out;

  float *p_sc, *p_scs;
  int   *p_idx, *p_idxs;
  void  *p_tmp;
  cudaGetSymbolAddress((void**)&p_sc,   g_sc);
  cudaGetSymbolAddress((void**)&p_scs,  g_scs);
  cudaGetSymbolAddress((void**)&p_idx,  g_idx);
  cudaGetSymbolAddress((void**)&p_idxs, g_idxs);
  cudaGetSymbolAddress(&p_tmp,          g_tmp);

  gemm_kernel<<<NPOS / 64, 256>>>(feat, wcls, bcls, wbbox, bbbox);
  decode_kernel<<<(NANCH + 255) / 256, 256>>>(anchors, img);

  // Scores in (0,1): bits 30-31 are zero for all keys -> 30-bit sort is exact.
  size_t tmp_bytes = sizeof(g_tmp);
  cub::DeviceRadixSort::SortPairsDescending(p_tmp, tmp_bytes, p_sc, p_scs,
                                            p_idx, p_idxs, NANCH, 0, 30);

  nms_kernel<<<1, 1024>>>(out, out_size);
}

// round 12
// speedup vs baseline: 3.2221x; 1.2835x over previous
#include <cuda_runtime.h>
#include <cub/cub.cuh>

#define NPOS    16384
#define NANCH   147456
#define NOUTC   54
#define MAXOUT  2000
#define BATCH   128

// ---------------- scratch (static device globals; no allocation) ----------------
__device__ float g_logits[NPOS * NOUTC];   // GEMM output (16384 x 54)
__device__ float g_sc[NANCH];              // scores
__device__ float g_x0[NANCH];
__device__ float g_y0[NANCH];
__device__ float g_x1[NANCH];
__device__ float g_y1[NANCH];
__device__ float g_ar[NANCH];
__device__ int   g_idx[NANCH];
__device__ float g_scs[NANCH];             // sorted scores
__device__ int   g_idxs[NANCH];            // sorted indices
__device__ unsigned char g_tmp[8 << 20];   // cub temp storage

// Unfused Cephes exp (exp variants proven output-invariant in rounds 4-7).
__device__ __forceinline__ float cephes_expf(float xin) {
  float x = fminf(xin, 88.3762626647950f);
  x = fmaxf(x, -88.3762626647949f);
  float fx = floorf(__fadd_rn(__fmul_rn(x, 1.44269504088896341f), 0.5f));
  float tmp = __fmul_rn(fx, 0.693359375f);
  float z   = __fmul_rn(fx, -2.12194440e-4f);
  x = __fsub_rn(x, tmp);
  x = __fsub_rn(x, z);
  z = __fmul_rn(x, x);
  float y = 1.9875691500E-4f;
  y = __fadd_rn(__fmul_rn(y, x), 1.3981999507E-3f);
  y = __fadd_rn(__fmul_rn(y, x), 8.3334519073E-3f);
  y = __fadd_rn(__fmul_rn(y, x), 4.1665795894E-2f);
  y = __fadd_rn(__fmul_rn(y, x), 1.6666665459E-1f);
  y = __fadd_rn(__fmul_rn(y, x), 5.0000001201E-1f);
  y = __fadd_rn(__fmul_rn(y, z), x);
  y = __fadd_rn(y, 1.0f);
  int n = (int)fx;
  float two_n = __int_as_float((n + 127) << 23);
  return __fmul_rn(y, two_n);
}

// ---------------- GEMM: (16384 x 1024) * (1024 x 54) ----------------
// PROVEN BIT-EXACT vs reference (round 10): cublas sliced1x4 replica —
// 4 k-slices, slice g owns interleaved sub-tiles k in [32t+8g, 32t+8g+8);
// private FMA chains, combined ((p0+p1)+p2)+p3. DO NOT change FMA order.
__global__ void __launch_bounds__(256) gemm_kernel(
    const float* __restrict__ A,
    const float* __restrict__ Wc, const float* __restrict__ Bc,
    const float* __restrict__ Wb, const float* __restrict__ Bb) {
  __shared__ float As[64][33];   // [m][k], padded
  __shared__ float Bs[32][64];   // [k][n]
  const int tid = threadIdx.x;
  const int m0  = blockIdx.x * 64;
  const int tm  = tid & 15;      // m-group: rows tm*4 .. tm*4+3
  const int tn  = tid >> 4;      // n-group: cols tn*4 .. tn*4+3
  const int kq  = tid & 7;       // A-load: k-quad
  const int mr  = tid >> 3;      // A-load: row (0..31, +32)

  float cur[4][4][4];   // [slice][mi][nj]
#pragma unroll
  for (int s = 0; s < 4; ++s)
#pragma unroll
    for (int i = 0; i < 4; ++i)
#pragma unroll
      for (int j = 0; j < 4; ++j) cur[s][i][j] = 0.f;

  for (int k0 = 0; k0 < 1024; k0 += 32) {
    float4 va = *(const float4*)(A + (size_t)(m0 + mr) * 1024 + k0 + kq * 4);
    float4 vb = *(const float4*)(A + (size_t)(m0 + mr + 32) * 1024 + k0 + kq * 4);
    As[mr][kq * 4 + 0] = va.x; As[mr][kq * 4 + 1] = va.y;
    As[mr][kq * 4 + 2] = va.z; As[mr][kq * 4 + 3] = va.w;
    As[mr + 32][kq * 4 + 0] = vb.x; As[mr + 32][kq * 4 + 1] = vb.y;
    As[mr + 32][kq * 4 + 2] = vb.z; As[mr + 32][kq * 4 + 3] = vb.w;
#pragma unroll
    for (int i = 0; i < 8; ++i) {
      int e = i * 256 + tid;
      int k = e >> 6, n = e & 63;
      float w = 0.f;
      if (n < 18)      w = Wc[(size_t)(k0 + k) * 18 + n];
      else if (n < 54) w = Wb[(size_t)(k0 + k) * 36 + (n - 18)];
      Bs[k][n] = w;
    }
    __syncthreads();
#pragma unroll
    for (int g = 0; g < 4; ++g) {   // slice g: k-subtile [8g, 8g+8)
#pragma unroll
      for (int kk = 0; kk < 8; ++kk) {
        int k = g * 8 + kk;
        float4 b4 = *(const float4*)&Bs[k][tn * 4];
        float a0 = As[tm * 4 + 0][k];
        float a1 = As[tm * 4 + 1][k];
        float a2 = As[tm * 4 + 2][k];
        float a3 = As[tm * 4 + 3][k];
        cur[g][0][0] = fmaf(a0, b4.x, cur[g][0][0]); cur[g][0][1] = fmaf(a0, b4.y, cur[g][0][1]);
        cur[g][0][2] = fmaf(a0, b4.z, cur[g][0][2]); cur[g][0][3] = fmaf(a0, b4.w, cur[g][0][3]);
        cur[g][1][0] = fmaf(a1, b4.x, cur[g][1][0]); cur[g][1][1] = fmaf(a1, b4.y, cur[g][1][1]);
        cur[g][1][2] = fmaf(a1, b4.z, cur[g][1][2]); cur[g][1][3] = fmaf(a1, b4.w, cur[g][1][3]);
        cur[g][2][0] = fmaf(a2, b4.x, cur[g][2][0]); cur[g][2][1] = fmaf(a2, b4.y, cur[g][2][1]);
        cur[g][2][2] = fmaf(a2, b4.z, cur[g][2][2]); cur[g][2][3] = fmaf(a2, b4.w, cur[g][2][3]);
        cur[g][3][0] = fmaf(a3, b4.x, cur[g][3][0]); cur[g][3][1] = fmaf(a3, b4.y, cur[g][3][1]);
        cur[g][3][2] = fmaf(a3, b4.z, cur[g][3][2]); cur[g][3][3] = fmaf(a3, b4.w, cur[g][3][3]);
      }
    }
    __syncthreads();
  }
#pragma unroll
  for (int i = 0; i < 4; ++i)
#pragma unroll
    for (int j = 0; j < 4; ++j) {
      int n = tn * 4 + j;
      if (n < 54) {
        float logit = __fadd_rn(cur[0][i][j], cur[1][i][j]);
        logit = __fadd_rn(logit, cur[2][i][j]);
        logit = __fadd_rn(logit, cur[3][i][j]);
        float bias = (n < 18) ? Bc[n] : Bb[n - 18];
        g_logits[(size_t)(m0 + tm * 4 + i) * NOUTC + n] = __fadd_rn(logit, bias);
      }
    }
}

// ---------------- decode: softmax-pair score + box decode/clip ----------------
__global__ void __launch_bounds__(256) decode_kernel(
    const float* __restrict__ anchors, const float* __restrict__ img) {
  int g = blockIdx.x * 256 + threadIdx.x;
  if (g >= NANCH) return;
  int p = g / 9, a = g - p * 9;
  const float* L = g_logits + (size_t)p * NOUTC;
  int c = 9 + a;
  float la = L[c], lb = L[c ^ 1];
  float m  = fmaxf(la, lb);
  float ea = cephes_expf(__fsub_rn(la, m));
  float eb = cephes_expf(__fsub_rn(lb, m));
  float score = __fdiv_rn(ea, __fadd_rn(ea, eb));

  float tx = L[18 + 4 * a + 0];
  float ty = L[18 + 4 * a + 1];
  float tw = L[18 + 4 * a + 2];
  float th = L[18 + 4 * a + 3];
  float a0 = anchors[4 * g + 0];
  float a1 = anchors[4 * g + 1];
  float a2 = anchors[4 * g + 2];
  float a3 = anchors[4 * g + 3];
  float w  = __fadd_rn(__fsub_rn(a3, a1), 1.0f);
  float h  = __fadd_rn(__fsub_rn(a2, a0), 1.0f);
  float xc = __fadd_rn(a0, __fmul_rn(0.5f, h));
  float yc = __fadd_rn(a1, __fmul_rn(0.5f, w));
  float xp = __fadd_rn(__fmul_rn(tx, h), xc);
  float yp = __fadd_rn(__fmul_rn(ty, w), yc);
  float wp = __fmul_rn(cephes_expf(tw), w);
  float hp = __fmul_rn(cephes_expf(th), h);
  float hh = __fmul_rn(0.5f, hp);
  float hw = __fmul_rn(0.5f, wp);
  float X0 = fmaxf(__fsub_rn(xp, hh), 0.f);
  float X1 = fminf(__fadd_rn(xp, hh), img[0]);
  float Y0 = fmaxf(__fsub_rn(yp, hw), 0.f);
  float Y1 = fminf(__fadd_rn(yp, hw), img[1]);

  g_sc[g] = score;
  g_x0[g] = X0; g_y0[g] = Y0; g_x1[g] = X1; g_y1[g] = Y1;
  g_ar[g] = __fmul_rn(fmaxf(__fsub_rn(X1, X0), 0.f), fmaxf(__fsub_rn(Y1, Y0), 0.f));
  g_idx[g] = g;
}

// IoU test, bit-exact vs reference:
//   iou = inter / (((aS + aC) - inter) + 1e-9) > 0.7
// Fast path: if iw<=0 or ih<=0 then inter==0 exactly and iou==0 — never >0.7,
// so the FDIV is skipped without changing any decision bit.
__device__ __forceinline__ bool iou_gt(float4 s, float sA, float4 c, float cA) {
  float iw = __fsub_rn(fminf(s.z, c.z), fmaxf(s.x, c.x));
  float ih = __fsub_rn(fminf(s.w, c.w), fmaxf(s.y, c.y));
  if (!(iw > 0.f && ih > 0.f)) return false;
  float inter = __fmul_rn(iw, ih);
  float denom = __fadd_rn(__fsub_rn(__fadd_rn(sA, cA), inter), 1e-9f);
  return __fdiv_rn(inter, denom) > 0.7f;
}

// ---------------- greedy NMS: 128-candidate batches, warp-parallel scan,
// full intra-batch suppression matrix, serial 128-step resolve ----------------
__global__ void __launch_bounds__(1024) nms_kernel(float* __restrict__ out, int out_size) {
  __shared__ float4 sbox[MAXOUT];        // selected boxes
  __shared__ float  sar[MAXOUT];         // selected areas
  __shared__ float4 bbox[BATCH];         // batch candidate boxes
  __shared__ float  barr[BATCH], bsc[BATCH];
  __shared__ int    supS[BATCH];         // suppressed-by-selected-set flags
  __shared__ unsigned rowS[BATCH][4];    // 128x128 earlier-suppresses matrix
  __shared__ int    ns_sh;
  const int tid  = threadIdx.x;
  const int wid  = tid >> 5;
  const int lane = tid & 31;

  for (int i = tid; i < out_size; i += 1024) out[i] = 0.f;
  if (tid == 0) ns_sh = 0;
  __syncthreads();

  int ns = 0;
  for (int jb = 0; jb < NANCH && ns < MAXOUT; jb += BATCH) {
    if (tid < BATCH) {
      int v = g_idxs[jb + tid];
      bbox[tid] = make_float4(g_x0[v], g_y0[v], g_x1[v], g_y1[v]);
      barr[tid] = g_ar[v];
      bsc[tid]  = g_scs[jb + tid];
    }
    __syncthreads();

    // Phase 1: each warp owns candidates {wid, 32+wid, 64+wid, 96+wid}.
    //  (a) test vs selected set (lanes stride over S)
    //  (b) build the 4 ballot words of the candidate's intra-batch row
#pragma unroll
    for (int q = 0; q < 4; ++q) {
      const int c = q * 32 + wid;
      const float4 cb = bbox[c];
      const float  ca = barr[c];
      bool sup = false;
      for (int s = lane; s < ns; s += 32)
        if (iou_gt(sbox[s], sar[s], cb, ca)) sup = true;
      unsigned anysup = __any_sync(0xffffffffu, sup);
      if (lane == 0) supS[c] = anysup ? 1 : 0;
#pragma unroll
      for (int g = 0; g < 4; ++g) {
        const int e = g * 32 + lane;
        bool ps = (e < c) && iou_gt(bbox[e], barr[e], cb, ca);
        unsigned prow = __ballot_sync(0xffffffffu, ps);
        if (lane == 0) rowS[c][g] = prow;
      }
    }
    __syncthreads();

    // Phase 2: warp 0 resolves the greedy recurrence (uniform serial loop)
    // and appends alive candidates in order.
    if (wid == 0) {
      unsigned alive[4] = {0u, 0u, 0u, 0u};
      for (int c = 0; c < BATCH; ++c) {
        if (!supS[c]) {
          unsigned conflict = (rowS[c][0] & alive[0]) | (rowS[c][1] & alive[1]) |
                              (rowS[c][2] & alive[2]) | (rowS[c][3] & alive[3]);
          if (conflict == 0u) alive[c >> 5] |= (1u << (c & 31));
        }
      }
      const int base = ns_sh;
      int pre = 0;
#pragma unroll
      for (int g = 0; g < 4; ++g) {
        unsigned am = alive[g];
        if ((am >> lane) & 1u) {
          int pos = base + pre + __popc(am & ((1u << lane) - 1u));
          if (pos < MAXOUT) {
            int c = g * 32 + lane;
            sbox[pos] = bbox[c];
            sar[pos]  = barr[c];
            if (pos * 4 + 3 < out_size) {
              out[pos * 4 + 0] = bbox[c].x; out[pos * 4 + 1] = bbox[c].y;
              out[pos * 4 + 2] = bbox[c].z; out[pos * 4 + 3] = bbox[c].w;
            }
            int so = 4 * MAXOUT + pos;
            if (so < out_size) out[so] = bsc[c];
          }
        }
        pre += __popc(am);
      }
      __syncwarp();
      if (lane == 0) {
        int nn = base + pre;
        ns_sh = (nn > MAXOUT) ? MAXOUT : nn;
      }
    }
    __syncthreads();
    ns = ns_sh;
  }
}

// ---------------- launch ----------------
extern "C" void kernel_launch(void* const* d_in, const int* in_sizes, int n_in,
                              void* d_out, int out_size) {
  const float* feat    = (const float*)d_in[0];
  const float* anchors = (const float*)d_in[1];
  const float* img     = (const float*)d_in[2];
  const float* wcls    = (const float*)d_in[3];
  const float* bcls    = (const float*)d_in[4];
  const float* wbbox   = (const float*)d_in[5];
  const float* bbbox   = (const float*)d_in[6];
  float* out = (float*)d_out;

  float *p_sc, *p_scs;
  int   *p_idx, *p_idxs;
  void  *p_tmp;
  cudaGetSymbolAddress((void**)&p_sc,   g_sc);
  cudaGetSymbolAddress((void**)&p_scs,  g_scs);
  cudaGetSymbolAddress((void**)&p_idx,  g_idx);
  cudaGetSymbolAddress((void**)&p_idxs, g_idxs);
  cudaGetSymbolAddress(&p_tmp,          g_tmp);

  gemm_kernel<<<NPOS / 64, 256>>>(feat, wcls, bcls, wbbox, bbbox);
  decode_kernel<<<(NANCH + 255) / 256, 256>>>(anchors, img);

  // Scores in (0,1): bits 30-31 are zero for all keys -> 30-bit sort is exact.
  size_t tmp_bytes = sizeof(g_tmp);
  cub::DeviceRadixSort::SortPairsDescending(p_tmp, tmp_bytes, p_sc, p_scs,
                                            p_idx, p_idxs, NANCH, 0, 30);

  nms_kernel<<<1, 1024>>>(out, out_size);
}